// round 1
// baseline (speedup 1.0000x reference)
#include <cuda_runtime.h>
#include <math.h>

#define BN_EPS 1e-5f

// Scratch (static device allocations; no cudaMalloc allowed)
__device__ float g_y1[16 * 128 * 64 * 64];   // conv1 output  (33.5 MB)
__device__ float g_y2[16 * 256 * 64 * 64];   // conv2 output  (67 MB)
__device__ float g_scores[16 * 256 * 256];   // attention     (4 MB)

// ---------------------------------------------------------------------------
// Fused conv3x3(SAME) + BN(running stats) + SiLU as implicit GEMM.
// M = CO (tile 128), N = 4096 pixels per batch (tile 128), K = CI*9 (tile 8).
// block = 256 threads (16x16), each thread computes an 8x8 micro-tile.
// ---------------------------------------------------------------------------
template <int CI>
__global__ __launch_bounds__(256)
void conv_bn_silu_kernel(const float* __restrict__ x,
                         const float* __restrict__ wgt,
                         const float* __restrict__ gamma,
                         const float* __restrict__ beta,
                         const float* __restrict__ mean,
                         const float* __restrict__ var,
                         float* __restrict__ out, int CO)
{
    constexpr int K = CI * 9;
    __shared__ float As[8][128];
    __shared__ float Bs[8][128];

    const int b  = blockIdx.z;
    const int bm = blockIdx.y;      // CO tile
    const int bn = blockIdx.x;      // pixel tile
    const int t  = threadIdx.x;
    const int tx = t & 15, ty = t >> 4;

    const float* xb = x + (size_t)b * CI * 4096;

    float acc[8][8];
#pragma unroll
    for (int i = 0; i < 8; ++i)
#pragma unroll
        for (int j = 0; j < 8; ++j) acc[i][j] = 0.f;

    const int a_row = t >> 1;            // 0..127
    const int a_cg  = (t & 1) * 4;       // 0 or 4
    const int b_kk  = t >> 5;            // 0..7
    const int b_n   = t & 31;            // 0..31, covers n = b_n + 32*u

    for (int kt = 0; kt < K / 8; ++kt) {
        // --- A tile: weights [CO, K] row-major ---
        {
            float4 v = *reinterpret_cast<const float4*>(
                wgt + (size_t)(bm * 128 + a_row) * K + kt * 8 + a_cg);
            As[a_cg + 0][a_row] = v.x;
            As[a_cg + 1][a_row] = v.y;
            As[a_cg + 2][a_row] = v.z;
            As[a_cg + 3][a_row] = v.w;
        }
        // --- B tile: im2col gather ---
        {
            int k  = kt * 8 + b_kk;
            int ci = k / 9;
            int r  = k - ci * 9;
            int dh = r / 3 - 1;
            int dw = (r - (r / 3) * 3) - 1;
            const float* src = xb + (size_t)ci * 4096;
#pragma unroll
            for (int u = 0; u < 4; ++u) {
                int n  = b_n + 32 * u;
                int p  = bn * 128 + n;
                int h  = p >> 6, w = p & 63;
                int hh = h + dh, ww = w + dw;
                float v = 0.f;
                if (hh >= 0 && hh < 64 && ww >= 0 && ww < 64)
                    v = src[hh * 64 + ww];
                Bs[b_kk][n] = v;
            }
        }
        __syncthreads();
#pragma unroll
        for (int kk = 0; kk < 8; ++kk) {
            float a[8], bv[8];
            *reinterpret_cast<float4*>(&a[0])  = *reinterpret_cast<float4*>(&As[kk][ty * 8]);
            *reinterpret_cast<float4*>(&a[4])  = *reinterpret_cast<float4*>(&As[kk][ty * 8 + 4]);
            *reinterpret_cast<float4*>(&bv[0]) = *reinterpret_cast<float4*>(&Bs[kk][tx * 8]);
            *reinterpret_cast<float4*>(&bv[4]) = *reinterpret_cast<float4*>(&Bs[kk][tx * 8 + 4]);
#pragma unroll
            for (int i = 0; i < 8; ++i)
#pragma unroll
                for (int j = 0; j < 8; ++j) acc[i][j] += a[i] * bv[j];
        }
        __syncthreads();
    }

    // Epilogue: BN (running stats) + SiLU
#pragma unroll
    for (int i = 0; i < 8; ++i) {
        int co = bm * 128 + ty * 8 + i;
        float sc = gamma[co] * rsqrtf(var[co] + BN_EPS);
        float sh = beta[co] - mean[co] * sc;
        float* dst = out + ((size_t)(b * CO + co)) * 4096 + bn * 128 + tx * 8;
#pragma unroll
        for (int j = 0; j < 8; ++j) {
            float y = acc[i][j] * sc + sh;
            dst[j] = y / (1.f + expf(-y));
        }
    }
}

// ---------------------------------------------------------------------------
// scores[b,c,d] = (1/16) * sum_n q[b,c,n] * q[b,d,n];  q = y2 [B,256,4096]
// 64x64 tile, K-tile 8, 256 threads, 4x4 per thread. grid (4,4,16).
// ---------------------------------------------------------------------------
__global__ __launch_bounds__(256)
void scores_kernel(const float* __restrict__ q, float* __restrict__ scores)
{
    __shared__ float As[8][64];
    __shared__ float Bs[8][64];

    const int b  = blockIdx.z;
    const int bm = blockIdx.y;
    const int bn = blockIdx.x;
    const int t  = threadIdx.x;
    const int tx = t & 15, ty = t >> 4;

    const float* qb = q + (size_t)b * 256 * 4096;

    float acc[4][4];
#pragma unroll
    for (int i = 0; i < 4; ++i)
#pragma unroll
        for (int j = 0; j < 4; ++j) acc[i][j] = 0.f;

    const int l   = t * 2;
    const int row = l >> 3;     // 0..63
    const int c   = l & 7;      // even

    for (int kt = 0; kt < 512; ++kt) {
        {
            float2 v = *reinterpret_cast<const float2*>(
                qb + (size_t)(bm * 64 + row) * 4096 + kt * 8 + c);
            As[c][row] = v.x; As[c + 1][row] = v.y;
            float2 u = *reinterpret_cast<const float2*>(
                qb + (size_t)(bn * 64 + row) * 4096 + kt * 8 + c);
            Bs[c][row] = u.x; Bs[c + 1][row] = u.y;
        }
        __syncthreads();
#pragma unroll
        for (int kk = 0; kk < 8; ++kk) {
            float a[4], bv[4];
            *reinterpret_cast<float4*>(a)  = *reinterpret_cast<float4*>(&As[kk][ty * 4]);
            *reinterpret_cast<float4*>(bv) = *reinterpret_cast<float4*>(&Bs[kk][tx * 4]);
#pragma unroll
            for (int i = 0; i < 4; ++i)
#pragma unroll
                for (int j = 0; j < 4; ++j) acc[i][j] += a[i] * bv[j];
        }
        __syncthreads();
    }

    const float inv_t = 1.f / 16.f;   // TEMPERATURE = sqrt(256)
#pragma unroll
    for (int i = 0; i < 4; ++i) {
        int cc = bm * 64 + ty * 4 + i;
#pragma unroll
        for (int j = 0; j < 4; ++j)
            scores[((size_t)b * 256 + cc) * 256 + bn * 64 + tx * 4 + j] = acc[i][j] * inv_t;
    }
}

// ---------------------------------------------------------------------------
// Row softmax in-place: 16*256 rows of 256. One block per row.
// ---------------------------------------------------------------------------
__global__ __launch_bounds__(256)
void softmax_kernel(float* __restrict__ s)
{
    __shared__ float redmax[8];
    __shared__ float redsum[8];
    float* r = s + (size_t)blockIdx.x * 256;
    const int t = threadIdx.x;

    float v = r[t];
    float m = v;
#pragma unroll
    for (int o = 16; o; o >>= 1) m = fmaxf(m, __shfl_xor_sync(0xffffffffu, m, o));
    if ((t & 31) == 0) redmax[t >> 5] = m;
    __syncthreads();
    m = redmax[0];
#pragma unroll
    for (int i = 1; i < 8; ++i) m = fmaxf(m, redmax[i]);

    float e = expf(v - m);
    float sum = e;
#pragma unroll
    for (int o = 16; o; o >>= 1) sum += __shfl_xor_sync(0xffffffffu, sum, o);
    if ((t & 31) == 0) redsum[t >> 5] = sum;
    __syncthreads();
    sum = 0.f;
#pragma unroll
    for (int i = 0; i < 8; ++i) sum += redsum[i];

    r[t] = e / sum;
}

// ---------------------------------------------------------------------------
// out[b,c,n] = x[b,c,n] + sum_d attn[b,c,d] * q[b,d,n]
// M=256 (tile 128), N=4096 (tile 128), K=256 (tile 8). grid (32,2,16).
// ---------------------------------------------------------------------------
__global__ __launch_bounds__(256)
void out_kernel(const float* __restrict__ attn,
                const float* __restrict__ q,
                const float* __restrict__ x,
                float* __restrict__ out)
{
    __shared__ float As[8][128];
    __shared__ float Bs[8][128];

    const int b  = blockIdx.z;
    const int bm = blockIdx.y;
    const int bn = blockIdx.x;
    const int t  = threadIdx.x;
    const int tx = t & 15, ty = t >> 4;

    const float* ab = attn + (size_t)b * 256 * 256;
    const float* qb = q + (size_t)b * 256 * 4096;

    float acc[8][8];
#pragma unroll
    for (int i = 0; i < 8; ++i)
#pragma unroll
        for (int j = 0; j < 8; ++j) acc[i][j] = 0.f;

    const int a_row = t >> 1;
    const int a_cg  = (t & 1) * 4;
    const int b_kk  = (t * 4) >> 7;    // 0..7
    const int b_n0  = (t * 4) & 127;   // multiple of 4

    for (int kt = 0; kt < 32; ++kt) {
        {
            float4 v = *reinterpret_cast<const float4*>(
                ab + (size_t)(bm * 128 + a_row) * 256 + kt * 8 + a_cg);
            As[a_cg + 0][a_row] = v.x;
            As[a_cg + 1][a_row] = v.y;
            As[a_cg + 2][a_row] = v.z;
            As[a_cg + 3][a_row] = v.w;
        }
        {
            float4 v = *reinterpret_cast<const float4*>(
                qb + (size_t)(kt * 8 + b_kk) * 4096 + bn * 128 + b_n0);
            Bs[b_kk][b_n0 + 0] = v.x;
            Bs[b_kk][b_n0 + 1] = v.y;
            Bs[b_kk][b_n0 + 2] = v.z;
            Bs[b_kk][b_n0 + 3] = v.w;
        }
        __syncthreads();
#pragma unroll
        for (int kk = 0; kk < 8; ++kk) {
            float a[8], bv[8];
            *reinterpret_cast<float4*>(&a[0])  = *reinterpret_cast<float4*>(&As[kk][ty * 8]);
            *reinterpret_cast<float4*>(&a[4])  = *reinterpret_cast<float4*>(&As[kk][ty * 8 + 4]);
            *reinterpret_cast<float4*>(&bv[0]) = *reinterpret_cast<float4*>(&Bs[kk][tx * 8]);
            *reinterpret_cast<float4*>(&bv[4]) = *reinterpret_cast<float4*>(&Bs[kk][tx * 8 + 4]);
#pragma unroll
            for (int i = 0; i < 8; ++i)
#pragma unroll
                for (int j = 0; j < 8; ++j) acc[i][j] += a[i] * bv[j];
        }
        __syncthreads();
    }

#pragma unroll
    for (int i = 0; i < 8; ++i) {
        int cc = bm * 128 + ty * 8 + i;
        size_t base = ((size_t)(b * 256 + cc)) * 4096 + bn * 128 + tx * 8;
#pragma unroll
        for (int j = 0; j < 8; ++j)
            out[base + j] = acc[i][j] + x[base + j];
    }
}

// ---------------------------------------------------------------------------
extern "C" void kernel_launch(void* const* d_in, const int* in_sizes, int n_in,
                              void* d_out, int out_size)
{
    const float* x  = (const float*)d_in[0];
    const float* w1 = (const float*)d_in[1];
    const float* g1 = (const float*)d_in[2];
    const float* b1 = (const float*)d_in[3];
    const float* m1 = (const float*)d_in[4];
    const float* v1 = (const float*)d_in[5];
    const float* w2 = (const float*)d_in[6];
    const float* g2 = (const float*)d_in[7];
    const float* b2 = (const float*)d_in[8];
    const float* m2 = (const float*)d_in[9];
    const float* v2 = (const float*)d_in[10];
    float* out = (float*)d_out;

    float *y1, *y2, *sc;
    cudaGetSymbolAddress((void**)&y1, g_y1);
    cudaGetSymbolAddress((void**)&y2, g_y2);
    cudaGetSymbolAddress((void**)&sc, g_scores);

    conv_bn_silu_kernel<256><<<dim3(32, 1, 16), 256>>>(x,  w1, g1, b1, m1, v1, y1, 128);
    conv_bn_silu_kernel<128><<<dim3(32, 2, 16), 256>>>(y1, w2, g2, b2, m2, v2, y2, 256);
    scores_kernel<<<dim3(4, 4, 16), 256>>>(y2, sc);
    softmax_kernel<<<4096, 256>>>(sc);
    out_kernel<<<dim3(32, 2, 16), 256>>>(sc, y2, x, out);
}

// round 4
// speedup vs baseline: 1.7106x; 1.7106x over previous
#include <cuda_runtime.h>
#include <cuda_bf16.h>
#include <math.h>
#include <stdint.h>

#define BN_EPS 1e-5f

// ---------------------------------------------------------------------------
// Global scratch (packed (hi,lo) bf16 pairs as uint32: hi = low 16 bits)
// ---------------------------------------------------------------------------
__device__ uint32_t g_xp  [16u*256*4096];   // x packed           (67 MB)
__device__ uint32_t g_w1p [128*2304];
__device__ uint32_t g_w2p [256*1152];
__device__ uint32_t g_y1p [16u*128*4096];   // conv1 out packed   (33 MB)
__device__ uint32_t g_y2p [16u*256*4096];   // conv2 out packed   (67 MB)
__device__ uint32_t g_y2tp[16u*256*4096];   // conv2 out, transposed [b][pix][c]
__device__ float    g_sc  [16u*256*256];    // scores fp32
__device__ uint32_t g_attnp[16u*256*256];   // softmax out packed

// ---------------------------------------------------------------------------
__device__ __forceinline__ uint32_t smem_u32(const void* p) {
    uint32_t a;
    asm("{ .reg .u64 t; cvta.to.shared.u64 t, %1; cvt.u32.u64 %0, t; }" : "=r"(a) : "l"(p));
    return a;
}
__device__ __forceinline__ uint32_t pack_hl(float v) {
    __nv_bfloat16 h = __float2bfloat16(v);
    float hf = __bfloat162float(h);
    __nv_bfloat16 l = __float2bfloat16(v - hf);
    return (uint32_t)__bfloat16_as_ushort(h) | ((uint32_t)__bfloat16_as_ushort(l) << 16);
}
__device__ __forceinline__ void ldsm_x4(uint32_t addr, uint32_t r[4]) {
    asm volatile("ldmatrix.sync.aligned.m8n8.x4.shared.b16 {%0,%1,%2,%3}, [%4];"
                 : "=r"(r[0]), "=r"(r[1]), "=r"(r[2]), "=r"(r[3]) : "r"(addr));
}
__device__ __forceinline__ void mma16816(float d[4], const uint32_t a[4],
                                         uint32_t b0, uint32_t b1) {
    asm volatile(
        "mma.sync.aligned.m16n8k16.row.col.f32.bf16.bf16.f32 "
        "{%0,%1,%2,%3}, {%4,%5,%6,%7}, {%8,%9}, {%0,%1,%2,%3};"
        : "+f"(d[0]), "+f"(d[1]), "+f"(d[2]), "+f"(d[3])
        : "r"(a[0]), "r"(a[1]), "r"(a[2]), "r"(a[3]), "r"(b0), "r"(b1));
}
__device__ __forceinline__ uint32_t sw128(uint32_t off) {
    return off ^ ((off >> 3) & 0x70);
}

// ---------------------------------------------------------------------------
// smem tile fills: [128 rows][64 bf16 = 128B], SW128 swizzled, hi/lo split
// ---------------------------------------------------------------------------
__device__ __forceinline__ void fill_plain(char* th, char* tl,
                                           const uint32_t* __restrict__ src, int ld,
                                           int row0, int kt, int t) {
#pragma unroll
    for (int i = 0; i < 8; ++i) {
        int task = t + i * 256;           // 2048 tasks: 128 rows x 16 groups
        int m = task >> 4, g = task & 15;
        uint4 u = *reinterpret_cast<const uint4*>(src + (size_t)(row0 + m) * ld + kt * 64 + g * 4);
        uint32_t h01 = (u.x & 0xFFFFu) | (u.y << 16);
        uint32_t h23 = (u.z & 0xFFFFu) | (u.w << 16);
        uint32_t l01 = (u.x >> 16) | (u.y & 0xFFFF0000u);
        uint32_t l23 = (u.z >> 16) | (u.w & 0xFFFF0000u);
        uint32_t swo = sw128(m * 128 + g * 8);
        *reinterpret_cast<uint2*>(th + swo) = make_uint2(h01, h23);
        *reinterpret_cast<uint2*>(tl + swo) = make_uint2(l01, l23);
    }
}

// im2col tile for conv3x3 SAME on 64x64 image; k = ci*9 + (dh+1)*3 + (dw+1)
__device__ __forceinline__ void fill_im2col(char* th, char* tl,
                                            const uint32_t* __restrict__ img,
                                            int kt, int pix0, int t) {
    const int n = t >> 1;                 // pixel within tile (0..127)
    const int jb = (t & 1) * 32;          // k-half
    const int p = pix0 + n;
    const int h = p >> 6, w = p & 63;
#pragma unroll 8
    for (int j2 = 0; j2 < 32; ++j2) {
        const int j  = jb + j2;
        const int k  = kt * 64 + j;
        const int ci = k / 9;
        const int r  = k - ci * 9;
        const int dh = r / 3 - 1;
        const int dw = (r - (r / 3) * 3) - 1;
        const int hh = h + dh, ww = w + dw;
        uint32_t v = 0;
        if ((unsigned)hh < 64u && (unsigned)ww < 64u)
            v = img[ci * 4096 + hh * 64 + ww];
        const uint32_t swo = sw128(n * 128 + j * 2);
        *reinterpret_cast<uint16_t*>(th + swo) = (uint16_t)v;
        *reinterpret_cast<uint16_t*>(tl + swo) = (uint16_t)(v >> 16);
    }
}

// ---------------------------------------------------------------------------
// Split-bf16 GEMM on HMMA (mma.sync m16n8k16).
// D[128 tile, 128 tile] = A[128,K] * B[128,K]^T, fp32 accum.
// MODE 0: conv (BN+SiLU -> packed), B = im2col(CI)
// MODE 1: scores (x 1/16 -> fp32)
// MODE 2: out (+ residual -> fp32)
// ---------------------------------------------------------------------------
template <int MODE, int CI>
__global__ __launch_bounds__(256)
void gemm_mma(const uint32_t* __restrict__ Ap, int lda,
              const uint32_t* __restrict__ Bp, int K,
              const float* __restrict__ p0, const float* __restrict__ p1,
              const float* __restrict__ p2, const float* __restrict__ p3,
              const float* __restrict__ resid,
              uint32_t* __restrict__ outp, float* __restrict__ outf)
{
    extern __shared__ char sm[];
    char* Ah = sm;
    char* Al = sm + 16384;
    char* Bh = sm + 32768;
    char* Bl = sm + 49152;

    const int t    = threadIdx.x;
    const int lane = t & 31, warp = t >> 5;
    const int wm   = (warp >> 1) * 32;    // warp row offset (0,32,64,96)
    const int wn   = (warp & 1) * 64;     // warp col offset (0,64)
    const int b  = blockIdx.z, bm = blockIdx.y, bn = blockIdx.x;

    const uint32_t sb = smem_u32(sm);

    const uint32_t* Ab;
    const uint32_t* Bb;
    if (MODE == 0)      { Ab = Ap;                          Bb = Bp + (size_t)b * CI * 4096; }
    else if (MODE == 1) { Ab = Ap + (size_t)b * 256 * 4096; Bb = Bp + (size_t)b * 256 * 4096; }
    else                { Ab = Ap + (size_t)b * 256 * 256;  Bb = Bp + (size_t)b * 4096 * 256; }
    constexpr int LDB = (MODE == 1) ? 4096 : 256;

    float acc[2][8][4];
#pragma unroll
    for (int i = 0; i < 2; ++i)
#pragma unroll
        for (int j = 0; j < 8; ++j)
#pragma unroll
            for (int q = 0; q < 4; ++q) acc[i][j][q] = 0.f;

    // ldmatrix lane address components (within a [row][128B] swizzled tile)
    const int a_row = (lane & 7) + ((lane >> 3) & 1) * 8;   // + chunk sel lane>>4
    const int a_chk = lane >> 4;
    const int b_row = (lane & 7) + ((lane >> 4) & 1) * 8;
    const int b_chk = (lane >> 3) & 1;

    const int nch = K / 64;
    for (int kt = 0; kt < nch; ++kt) {
        fill_plain(Ah, Al, Ab, lda, bm * 128, kt, t);
        if (MODE == 0) fill_im2col(Bh, Bl, Bb, kt, bn * 128, t);
        else           fill_plain(Bh, Bl, Bb, LDB, bn * 128, kt, t);
        __syncthreads();

#pragma unroll
        for (int ks = 0; ks < 4; ++ks) {
            uint32_t ah[2][4], al[2][4];
#pragma unroll
            for (int mt = 0; mt < 2; ++mt) {
                uint32_t off = sw128((wm + mt * 16 + a_row) * 128 + (ks * 2 + a_chk) * 16);
                ldsm_x4(sb + (uint32_t)(Ah - sm) + off, ah[mt]);
                ldsm_x4(sb + (uint32_t)(Al - sm) + off, al[mt]);
            }
#pragma unroll
            for (int ng = 0; ng < 4; ++ng) {
                uint32_t bh[4], bl[4];
                uint32_t off = sw128((wn + ng * 16 + b_row) * 128 + (ks * 2 + b_chk) * 16);
                ldsm_x4(sb + (uint32_t)(Bh - sm) + off, bh);
                ldsm_x4(sb + (uint32_t)(Bl - sm) + off, bl);
#pragma unroll
                for (int mt = 0; mt < 2; ++mt) {
                    mma16816(acc[mt][2 * ng],     ah[mt], bh[0], bh[1]);
                    mma16816(acc[mt][2 * ng],     ah[mt], bl[0], bl[1]);
                    mma16816(acc[mt][2 * ng],     al[mt], bh[0], bh[1]);
                    mma16816(acc[mt][2 * ng + 1], ah[mt], bh[2], bh[3]);
                    mma16816(acc[mt][2 * ng + 1], ah[mt], bl[2], bl[3]);
                    mma16816(acc[mt][2 * ng + 1], al[mt], bh[2], bh[3]);
                }
            }
        }
        __syncthreads();
    }

    // ----------------------- epilogue -----------------------
    const int r0 = bm * 128 + wm + (lane >> 2);
    const int c0 = bn * 128 + wn + (lane & 3) * 2;

    if (MODE == 0) {
        const int CO = gridDim.y * 128;
#pragma unroll
        for (int mt = 0; mt < 2; ++mt) {
#pragma unroll
            for (int half = 0; half < 2; ++half) {
                const int co = r0 + mt * 16 + half * 8;
                const float scl = p0[co] * rsqrtf(p3[co] + BN_EPS);
                const float shf = p1[co] - p2[co] * scl;
                uint32_t* dst = outp + ((size_t)(b * CO + co)) * 4096;
#pragma unroll
                for (int nt = 0; nt < 8; ++nt) {
                    float y0 = acc[mt][nt][2 * half]     * scl + shf;
                    float y1 = acc[mt][nt][2 * half + 1] * scl + shf;
                    y0 = y0 / (1.f + expf(-y0));
                    y1 = y1 / (1.f + expf(-y1));
                    *reinterpret_cast<uint2*>(dst + c0 + nt * 8) =
                        make_uint2(pack_hl(y0), pack_hl(y1));
                }
            }
        }
    } else if (MODE == 1) {
#pragma unroll
        for (int mt = 0; mt < 2; ++mt) {
#pragma unroll
            for (int half = 0; half < 2; ++half) {
                const int c = r0 + mt * 16 + half * 8;
                float* dst = outf + ((size_t)b * 256 + c) * 256;
#pragma unroll
                for (int nt = 0; nt < 8; ++nt) {
                    *reinterpret_cast<float2*>(dst + c0 + nt * 8) =
                        make_float2(acc[mt][nt][2 * half] * 0.0625f,
                                    acc[mt][nt][2 * half + 1] * 0.0625f);
                }
            }
        }
    } else {
#pragma unroll
        for (int mt = 0; mt < 2; ++mt) {
#pragma unroll
            for (int half = 0; half < 2; ++half) {
                const int c = r0 + mt * 16 + half * 8;
                const size_t base = ((size_t)(b * 256 + c)) * 4096;
#pragma unroll
                for (int nt = 0; nt < 8; ++nt) {
                    float2 rx = *reinterpret_cast<const float2*>(resid + base + c0 + nt * 8);
                    *reinterpret_cast<float2*>(outf + base + c0 + nt * 8) =
                        make_float2(acc[mt][nt][2 * half] + rx.x,
                                    acc[mt][nt][2 * half + 1] + rx.y);
                }
            }
        }
    }
}

// ---------------------------------------------------------------------------
__global__ __launch_bounds__(256) void cvt_split4(const float4* __restrict__ in,
                                                  uint4* __restrict__ out, int n4) {
    int i = blockIdx.x * 256 + threadIdx.x;
    if (i < n4) {
        float4 v = in[i];
        out[i] = make_uint4(pack_hl(v.x), pack_hl(v.y), pack_hl(v.z), pack_hl(v.w));
    }
}

__global__ void transpose_pack(const uint32_t* __restrict__ src, uint32_t* __restrict__ dst) {
    __shared__ uint32_t tile[32][33];
    const int b  = blockIdx.z;
    const int p0 = blockIdx.x * 32, c0 = blockIdx.y * 32;
    const uint32_t* s = src + (size_t)b * 256 * 4096;
    uint32_t*       d = dst + (size_t)b * 256 * 4096;
    const int x = threadIdx.x, y = threadIdx.y;
#pragma unroll
    for (int i = y; i < 32; i += 8) tile[i][x] = s[(size_t)(c0 + i) * 4096 + p0 + x];
    __syncthreads();
#pragma unroll
    for (int i = y; i < 32; i += 8) d[(size_t)(p0 + i) * 256 + c0 + x] = tile[x][i];
}

__global__ __launch_bounds__(256) void softmax_pack(const float* __restrict__ s,
                                                    uint32_t* __restrict__ ap) {
    __shared__ float redmax[8];
    __shared__ float redsum[8];
    const float* r = s + (size_t)blockIdx.x * 256;
    const int t = threadIdx.x;

    float v = r[t];
    float m = v;
#pragma unroll
    for (int o = 16; o; o >>= 1) m = fmaxf(m, __shfl_xor_sync(0xffffffffu, m, o));
    if ((t & 31) == 0) redmax[t >> 5] = m;
    __syncthreads();
    m = redmax[0];
#pragma unroll
    for (int i = 1; i < 8; ++i) m = fmaxf(m, redmax[i]);

    float e = expf(v - m);
    float sum = e;
#pragma unroll
    for (int o = 16; o; o >>= 1) sum += __shfl_xor_sync(0xffffffffu, sum, o);
    if ((t & 31) == 0) redsum[t >> 5] = sum;
    __syncthreads();
    sum = 0.f;
#pragma unroll
    for (int i = 0; i < 8; ++i) sum += redsum[i];

    ap[(size_t)blockIdx.x * 256 + t] = pack_hl(e / sum);
}

// ---------------------------------------------------------------------------
extern "C" void kernel_launch(void* const* d_in, const int* in_sizes, int n_in,
                              void* d_out, int out_size)
{
    const float* x  = (const float*)d_in[0];
    const float* w1 = (const float*)d_in[1];
    const float* g1 = (const float*)d_in[2];
    const float* b1 = (const float*)d_in[3];
    const float* m1 = (const float*)d_in[4];
    const float* v1 = (const float*)d_in[5];
    const float* w2 = (const float*)d_in[6];
    const float* g2 = (const float*)d_in[7];
    const float* b2 = (const float*)d_in[8];
    const float* m2 = (const float*)d_in[9];
    const float* v2 = (const float*)d_in[10];
    float* out = (float*)d_out;

    uint32_t *xp, *w1p, *w2p, *y1p, *y2p, *y2tp, *attnp;
    float* sc;
    cudaGetSymbolAddress((void**)&xp,   g_xp);
    cudaGetSymbolAddress((void**)&w1p,  g_w1p);
    cudaGetSymbolAddress((void**)&w2p,  g_w2p);
    cudaGetSymbolAddress((void**)&y1p,  g_y1p);
    cudaGetSymbolAddress((void**)&y2p,  g_y2p);
    cudaGetSymbolAddress((void**)&y2tp, g_y2tp);
    cudaGetSymbolAddress((void**)&sc,   g_sc);
    cudaGetSymbolAddress((void**)&attnp, g_attnp);

    const int SMB = 65536;
    cudaFuncSetAttribute(gemm_mma<0, 256>, cudaFuncAttributeMaxDynamicSharedMemorySize, SMB);
    cudaFuncSetAttribute(gemm_mma<0, 128>, cudaFuncAttributeMaxDynamicSharedMemorySize, SMB);
    cudaFuncSetAttribute(gemm_mma<1, 0>,   cudaFuncAttributeMaxDynamicSharedMemorySize, SMB);
    cudaFuncSetAttribute(gemm_mma<2, 0>,   cudaFuncAttributeMaxDynamicSharedMemorySize, SMB);

    // Pack inputs to (hi,lo) bf16
    cvt_split4<<<16384, 256>>>((const float4*)x,  (uint4*)xp,  16u * 256 * 4096 / 4);
    cvt_split4<<<288,   256>>>((const float4*)w1, (uint4*)w1p, 128 * 2304 / 4);
    cvt_split4<<<288,   256>>>((const float4*)w2, (uint4*)w2p, 256 * 1152 / 4);

    // conv1: [B,256,64,64] -> [B,128,64,64]
    gemm_mma<0, 256><<<dim3(32, 1, 16), 256, SMB>>>(
        w1p, 2304, xp, 2304, g1, b1, m1, v1, nullptr, y1p, nullptr);
    // conv2: [B,128,64,64] -> [B,256,64,64]
    gemm_mma<0, 128><<<dim3(32, 2, 16), 256, SMB>>>(
        w2p, 1152, y1p, 1152, g2, b2, m2, v2, nullptr, y2p, nullptr);
    // transpose y2 for the out GEMM
    transpose_pack<<<dim3(128, 8, 16), dim3(32, 8)>>>(y2p, y2tp);
    // scores = (q q^T)/16
    gemm_mma<1, 0><<<dim3(2, 2, 16), 256, SMB>>>(
        y2p, 4096, y2p, 4096, nullptr, nullptr, nullptr, nullptr, nullptr, nullptr, sc);
    // softmax -> packed attn
    softmax_pack<<<4096, 256>>>(sc, attnp);
    // out = attn * q + x  (FIX: bn must cover 4096/128 = 32 tiles)
    gemm_mma<2, 0><<<dim3(32, 2, 16), 256, SMB>>>(
        attnp, 256, y2tp, 256, nullptr, nullptr, nullptr, nullptr, x, nullptr, out);
}

// round 5
// speedup vs baseline: 3.2221x; 1.8835x over previous
#include <cuda_runtime.h>
#include <cuda_bf16.h>
#include <math.h>
#include <stdint.h>

#define BN_EPS 1e-5f

// ---------------------------------------------------------------------------
// Global scratch: hi/lo bf16 planes for all GEMM operands
// ---------------------------------------------------------------------------
__device__ __nv_bfloat16 g_w1h[128*2304],  g_w1l[128*2304];    // k = r*256+ci
__device__ __nv_bfloat16 g_w2h[256*1152],  g_w2l[256*1152];    // k = r*128+ci
__device__ __nv_bfloat16 g_xth[16u*4096*256], g_xtl[16u*4096*256];   // x^T [b][p][ci]
__device__ uint32_t      g_y1p[16u*128*4096];                        // conv1 out packed [b][c][p]
__device__ __nv_bfloat16 g_y1th[16u*4096*128], g_y1tl[16u*4096*128]; // y1^T [b][p][ci]
__device__ uint32_t      g_y2p[16u*256*4096];                        // conv2 out packed [b][c][p]
__device__ __nv_bfloat16 g_y2h[16u*256*4096],  g_y2l[16u*256*4096];  // y2   [b][c][p]
__device__ __nv_bfloat16 g_y2th[16u*4096*256], g_y2tl[16u*4096*256]; // y2^T [b][p][c]
__device__ float         g_sc[16u*256*256];
__device__ __nv_bfloat16 g_ath[16u*256*256], g_atl[16u*256*256];     // attn planes

// ---------------------------------------------------------------------------
__device__ __forceinline__ uint32_t smem_u32(const void* p) {
    uint32_t a;
    asm("{ .reg .u64 t; cvta.to.shared.u64 t, %1; cvt.u32.u64 %0, t; }" : "=r"(a) : "l"(p));
    return a;
}
__device__ __forceinline__ uint32_t pack_hl(float v) {
    __nv_bfloat16 h = __float2bfloat16(v);
    float hf = __bfloat162float(h);
    __nv_bfloat16 l = __float2bfloat16(v - hf);
    return (uint32_t)__bfloat16_as_ushort(h) | ((uint32_t)__bfloat16_as_ushort(l) << 16);
}
__device__ __forceinline__ void ldsm_x4(uint32_t addr, uint32_t r[4]) {
    asm volatile("ldmatrix.sync.aligned.m8n8.x4.shared.b16 {%0,%1,%2,%3}, [%4];"
                 : "=r"(r[0]), "=r"(r[1]), "=r"(r[2]), "=r"(r[3]) : "r"(addr));
}
__device__ __forceinline__ void mma16816(float d[4], const uint32_t a[4],
                                         uint32_t b0, uint32_t b1) {
    asm volatile(
        "mma.sync.aligned.m16n8k16.row.col.f32.bf16.bf16.f32 "
        "{%0,%1,%2,%3}, {%4,%5,%6,%7}, {%8,%9}, {%0,%1,%2,%3};"
        : "+f"(d[0]), "+f"(d[1]), "+f"(d[2]), "+f"(d[3])
        : "r"(a[0]), "r"(a[1]), "r"(a[2]), "r"(a[3]), "r"(b0), "r"(b1));
}
__device__ __forceinline__ uint32_t sw128(uint32_t off) {
    return off ^ ((off >> 3) & 0x70);
}
__device__ __forceinline__ void cp16(uint32_t dst, const void* src, int sz) {
    asm volatile("cp.async.cg.shared.global [%0], [%1], 16, %2;"
                 :: "r"(dst), "l"(src), "r"(sz) : "memory");
}
__device__ __forceinline__ void cp_commit() {
    asm volatile("cp.async.commit_group;" ::: "memory");
}

// ---------------------------------------------------------------------------
// Split-bf16 GEMM on HMMA, cp.async double-buffered.
// D[128,128] tile = A[128,K] * B[128,K]^T, fp32 accum.
// MODE 0: conv (BN+SiLU -> packed out), B = shifted transposed image planes
// MODE 1: scores (x 1/16 -> fp32)
// MODE 2: out (+ residual -> fp32)
// Stage layout (64KB): Ah +0, Al +16384, Bh +32768, Bl +49152.
// ---------------------------------------------------------------------------
template <int MODE, int CI>
__global__ __launch_bounds__(256, 1)
void gemm_cp(const __nv_bfloat16* __restrict__ Agh, const __nv_bfloat16* __restrict__ Agl, int lda,
             const __nv_bfloat16* __restrict__ Bgh, const __nv_bfloat16* __restrict__ Bgl, int K,
             const float* __restrict__ p0, const float* __restrict__ p1,
             const float* __restrict__ p2, const float* __restrict__ p3,
             const float* __restrict__ resid,
             uint32_t* __restrict__ outp, float* __restrict__ outf)
{
    extern __shared__ char sm[];
    const int t    = threadIdx.x;
    const int lane = t & 31, warp = t >> 5;
    const int wm   = (warp >> 1) * 32;
    const int wn   = (warp & 1) * 64;
    const int b = blockIdx.z, bm = blockIdx.y, bn = blockIdx.x;
    const uint32_t sb = smem_u32(sm);

    const __nv_bfloat16 *Abh, *Abl, *Bbh, *Bbl;
    if (MODE == 0) {
        Abh = Agh; Abl = Agl;
        Bbh = Bgh + (size_t)b * 4096 * CI; Bbl = Bgl + (size_t)b * 4096 * CI;
    } else if (MODE == 1) {
        size_t o = (size_t)b * 256 * 4096;
        Abh = Agh + o; Abl = Agl + o; Bbh = Bgh + o; Bbl = Bgl + o;
    } else {
        size_t oa = (size_t)b * 256 * 256, ob = (size_t)b * 4096 * 256;
        Abh = Agh + oa; Abl = Agl + oa; Bbh = Bgh + ob; Bbl = Bgl + ob;
    }
    const int ldb = (MODE == 1) ? 4096 : 256;   // unused for MODE 0

    float acc[2][8][4];
#pragma unroll
    for (int i = 0; i < 2; ++i)
#pragma unroll
        for (int j = 0; j < 8; ++j)
#pragma unroll
            for (int q = 0; q < 4; ++q) acc[i][j][q] = 0.f;

    const int a_row = (lane & 7) + ((lane >> 3) & 1) * 8;
    const int a_chk = lane >> 4;
    const int b_row = (lane & 7) + ((lane >> 4) & 1) * 8;
    const int b_chk = (lane >> 3) & 1;

    auto prefetch = [&](int kt, int stage) {
        const uint32_t base = sb + stage * 65536;
        // ---- A planes ----
#pragma unroll
        for (int i = 0; i < 4; ++i) {
            const int task = t + i * 256, m = task >> 3, g = task & 7;
            const size_t so = (size_t)(bm * 128 + m) * lda + kt * 64 + g * 8;
            const uint32_t d = sw128(m * 128 + g * 16);
            cp16(base + d,         Abh + so, 16);
            cp16(base + 16384 + d, Abl + so, 16);
        }
        // ---- B planes ----
        if (MODE == 0) {
            constexpr int CPR = CI / 64;       // chunks per 3x3 tap
            const int r  = kt / CPR;
            const int ci0 = (kt - r * CPR) * 64;
            const int dh = r / 3 - 1, dw = (r - (r / 3) * 3) - 1;
#pragma unroll
            for (int i = 0; i < 4; ++i) {
                const int task = t + i * 256, m = task >> 3, g = task & 7;
                const int p = bn * 128 + m, h = p >> 6, w = p & 63;
                const int hh = h + dh, ww = w + dw;
                const bool ok = ((unsigned)hh < 64u) && ((unsigned)ww < 64u);
                const size_t so = ok ? (size_t)((hh << 6) + ww) * CI + ci0 + g * 8 : 0;
                const int sz = ok ? 16 : 0;
                const uint32_t d = sw128(m * 128 + g * 16);
                cp16(base + 32768 + d, Bbh + so, sz);
                cp16(base + 49152 + d, Bbl + so, sz);
            }
        } else {
#pragma unroll
            for (int i = 0; i < 4; ++i) {
                const int task = t + i * 256, m = task >> 3, g = task & 7;
                const size_t so = (size_t)(bn * 128 + m) * ldb + kt * 64 + g * 8;
                const uint32_t d = sw128(m * 128 + g * 16);
                cp16(base + 32768 + d, Bbh + so, 16);
                cp16(base + 49152 + d, Bbl + so, 16);
            }
        }
    };

    const int nch = K / 64;
    prefetch(0, 0);
    cp_commit();

    for (int kt = 0; kt < nch; ++kt) {
        const int stage = kt & 1;
        if (kt + 1 < nch) {
            prefetch(kt + 1, stage ^ 1);
            cp_commit();
            asm volatile("cp.async.wait_group 1;" ::: "memory");
        } else {
            asm volatile("cp.async.wait_group 0;" ::: "memory");
        }
        __syncthreads();

        const uint32_t base = sb + stage * 65536;
#pragma unroll
        for (int ks = 0; ks < 4; ++ks) {
            uint32_t ah[2][4], al[2][4];
#pragma unroll
            for (int mt = 0; mt < 2; ++mt) {
                uint32_t off = sw128((wm + mt * 16 + a_row) * 128 + (ks * 2 + a_chk) * 16);
                ldsm_x4(base + off,         ah[mt]);
                ldsm_x4(base + 16384 + off, al[mt]);
            }
#pragma unroll
            for (int ng = 0; ng < 4; ++ng) {
                uint32_t bh[4], bl[4];
                uint32_t off = sw128((wn + ng * 16 + b_row) * 128 + (ks * 2 + b_chk) * 16);
                ldsm_x4(base + 32768 + off, bh);
                ldsm_x4(base + 49152 + off, bl);
#pragma unroll
                for (int mt = 0; mt < 2; ++mt) {
                    mma16816(acc[mt][2 * ng],     ah[mt], bh[0], bh[1]);
                    mma16816(acc[mt][2 * ng],     ah[mt], bl[0], bl[1]);
                    mma16816(acc[mt][2 * ng],     al[mt], bh[0], bh[1]);
                    mma16816(acc[mt][2 * ng + 1], ah[mt], bh[2], bh[3]);
                    mma16816(acc[mt][2 * ng + 1], ah[mt], bl[2], bl[3]);
                    mma16816(acc[mt][2 * ng + 1], al[mt], bh[2], bh[3]);
                }
            }
        }
        __syncthreads();
    }

    // ----------------------- epilogue -----------------------
    const int r0 = bm * 128 + wm + (lane >> 2);
    const int c0 = bn * 128 + wn + (lane & 3) * 2;

    if (MODE == 0) {
        const int CO = gridDim.y * 128;
#pragma unroll
        for (int mt = 0; mt < 2; ++mt) {
#pragma unroll
            for (int half = 0; half < 2; ++half) {
                const int co = r0 + mt * 16 + half * 8;
                const float scl = p0[co] * rsqrtf(p3[co] + BN_EPS);
                const float shf = p1[co] - p2[co] * scl;
                uint32_t* dst = outp + ((size_t)(b * CO + co)) * 4096;
#pragma unroll
                for (int nt = 0; nt < 8; ++nt) {
                    float y0 = acc[mt][nt][2 * half]     * scl + shf;
                    float y1 = acc[mt][nt][2 * half + 1] * scl + shf;
                    y0 = y0 / (1.f + expf(-y0));
                    y1 = y1 / (1.f + expf(-y1));
                    *reinterpret_cast<uint2*>(dst + c0 + nt * 8) =
                        make_uint2(pack_hl(y0), pack_hl(y1));
                }
            }
        }
    } else if (MODE == 1) {
#pragma unroll
        for (int mt = 0; mt < 2; ++mt) {
#pragma unroll
            for (int half = 0; half < 2; ++half) {
                const int c = r0 + mt * 16 + half * 8;
                float* dst = outf + ((size_t)b * 256 + c) * 256;
#pragma unroll
                for (int nt = 0; nt < 8; ++nt) {
                    *reinterpret_cast<float2*>(dst + c0 + nt * 8) =
                        make_float2(acc[mt][nt][2 * half] * 0.0625f,
                                    acc[mt][nt][2 * half + 1] * 0.0625f);
                }
            }
        }
    } else {
#pragma unroll
        for (int mt = 0; mt < 2; ++mt) {
#pragma unroll
            for (int half = 0; half < 2; ++half) {
                const int c = r0 + mt * 16 + half * 8;
                const size_t base2 = ((size_t)(b * 256 + c)) * 4096;
#pragma unroll
                for (int nt = 0; nt < 8; ++nt) {
                    float2 rx = *reinterpret_cast<const float2*>(resid + base2 + c0 + nt * 8);
                    *reinterpret_cast<float2*>(outf + base2 + c0 + nt * 8) =
                        make_float2(acc[mt][nt][2 * half] + rx.x,
                                    acc[mt][nt][2 * half + 1] + rx.y);
                }
            }
        }
    }
}

// ---------------------------------------------------------------------------
// Pack / reorder helpers
// ---------------------------------------------------------------------------
// weights OIHW [co][ci][3][3] -> planes [co][r*CI+ci]
__global__ __launch_bounds__(256) void w_reorder(const float* __restrict__ w,
                                                 __nv_bfloat16* __restrict__ wh,
                                                 __nv_bfloat16* __restrict__ wl,
                                                 int CO, int CIc) {
    int idx = blockIdx.x * 256 + threadIdx.x;
    int total = CO * CIc * 9;
    if (idx >= total) return;
    int K  = CIc * 9;
    int co = idx / K;
    int rem = idx - co * K;
    int r  = rem / CIc;
    int ci = rem - r * CIc;
    uint32_t pl = pack_hl(w[(size_t)co * K + ci * 9 + r]);
    wh[idx] = __ushort_as_bfloat16((uint16_t)pl);
    wl[idx] = __ushort_as_bfloat16((uint16_t)(pl >> 16));
}

// x fp32 [b][c][4096] -> transposed planes [b][p][C], C=256
__global__ void x_tr_split(const float* __restrict__ x,
                           __nv_bfloat16* __restrict__ xh, __nv_bfloat16* __restrict__ xl) {
    __shared__ float tile[32][33];
    const int b = blockIdx.z, p0 = blockIdx.x * 32, c0 = blockIdx.y * 32;
    const float* s = x + (size_t)b * 256 * 4096;
    const int tx = threadIdx.x, ty = threadIdx.y;
#pragma unroll
    for (int i = ty; i < 32; i += 8) tile[i][tx] = s[(size_t)(c0 + i) * 4096 + p0 + tx];
    __syncthreads();
#pragma unroll
    for (int i = ty; i < 32; i += 8) {
        uint32_t pl = pack_hl(tile[tx][i]);
        size_t d = (size_t)(b * 4096 + p0 + i) * 256 + c0 + tx;
        xh[d] = __ushort_as_bfloat16((uint16_t)pl);
        xl[d] = __ushort_as_bfloat16((uint16_t)(pl >> 16));
    }
}

// packed uint32 [b][C][4096] -> transposed planes [b][p][C]
__global__ void split_tr(const uint32_t* __restrict__ src,
                         __nv_bfloat16* __restrict__ th, __nv_bfloat16* __restrict__ tl, int C) {
    __shared__ uint32_t tile[32][33];
    const int b = blockIdx.z, p0 = blockIdx.x * 32, c0 = blockIdx.y * 32;
    const uint32_t* s = src + (size_t)b * C * 4096;
    const int tx = threadIdx.x, ty = threadIdx.y;
#pragma unroll
    for (int i = ty; i < 32; i += 8) tile[i][tx] = s[(size_t)(c0 + i) * 4096 + p0 + tx];
    __syncthreads();
#pragma unroll
    for (int i = ty; i < 32; i += 8) {
        uint32_t v = tile[tx][i];
        size_t d = (size_t)(b * 4096 + p0 + i) * C + c0 + tx;
        th[d] = __ushort_as_bfloat16((uint16_t)v);
        tl[d] = __ushort_as_bfloat16((uint16_t)(v >> 16));
    }
}

// packed uint32 -> same-layout hi/lo planes (x2 vectorized)
__global__ __launch_bounds__(256) void split_lin(const uint32_t* __restrict__ src,
                                                 __nv_bfloat16* __restrict__ h,
                                                 __nv_bfloat16* __restrict__ l, int n2) {
    int i = blockIdx.x * 256 + threadIdx.x;
    if (i < n2) {
        uint2 v = reinterpret_cast<const uint2*>(src)[i];
        uint32_t hp = (v.x & 0xFFFFu) | (v.y << 16);
        uint32_t lp = (v.x >> 16) | (v.y & 0xFFFF0000u);
        reinterpret_cast<uint32_t*>(h)[i] = hp;
        reinterpret_cast<uint32_t*>(l)[i] = lp;
    }
}

__global__ __launch_bounds__(256) void softmax_split(const float* __restrict__ s,
                                                     __nv_bfloat16* __restrict__ ah,
                                                     __nv_bfloat16* __restrict__ al) {
    __shared__ float redmax[8];
    __shared__ float redsum[8];
    const float* r = s + (size_t)blockIdx.x * 256;
    const int t = threadIdx.x;

    float v = r[t];
    float m = v;
#pragma unroll
    for (int o = 16; o; o >>= 1) m = fmaxf(m, __shfl_xor_sync(0xffffffffu, m, o));
    if ((t & 31) == 0) redmax[t >> 5] = m;
    __syncthreads();
    m = redmax[0];
#pragma unroll
    for (int i = 1; i < 8; ++i) m = fmaxf(m, redmax[i]);

    float e = expf(v - m);
    float sum = e;
#pragma unroll
    for (int o = 16; o; o >>= 1) sum += __shfl_xor_sync(0xffffffffu, sum, o);
    if ((t & 31) == 0) redsum[t >> 5] = sum;
    __syncthreads();
    sum = 0.f;
#pragma unroll
    for (int i = 0; i < 8; ++i) sum += redsum[i];

    uint32_t pl = pack_hl(e / sum);
    size_t idx = (size_t)blockIdx.x * 256 + t;
    ah[idx] = __ushort_as_bfloat16((uint16_t)pl);
    al[idx] = __ushort_as_bfloat16((uint16_t)(pl >> 16));
}

// ---------------------------------------------------------------------------
extern "C" void kernel_launch(void* const* d_in, const int* in_sizes, int n_in,
                              void* d_out, int out_size)
{
    const float* x  = (const float*)d_in[0];
    const float* w1 = (const float*)d_in[1];
    const float* g1 = (const float*)d_in[2];
    const float* b1 = (const float*)d_in[3];
    const float* m1 = (const float*)d_in[4];
    const float* v1 = (const float*)d_in[5];
    const float* w2 = (const float*)d_in[6];
    const float* g2 = (const float*)d_in[7];
    const float* b2 = (const float*)d_in[8];
    const float* m2 = (const float*)d_in[9];
    const float* v2 = (const float*)d_in[10];
    float* out = (float*)d_out;

    __nv_bfloat16 *w1h, *w1l, *w2h, *w2l, *xth, *xtl, *y1th, *y1tl;
    __nv_bfloat16 *y2h, *y2l, *y2th, *y2tl, *ath, *atl;
    uint32_t *y1p, *y2p;
    float* sc;
    cudaGetSymbolAddress((void**)&w1h, g_w1h);  cudaGetSymbolAddress((void**)&w1l, g_w1l);
    cudaGetSymbolAddress((void**)&w2h, g_w2h);  cudaGetSymbolAddress((void**)&w2l, g_w2l);
    cudaGetSymbolAddress((void**)&xth, g_xth);  cudaGetSymbolAddress((void**)&xtl, g_xtl);
    cudaGetSymbolAddress((void**)&y1p, g_y1p);
    cudaGetSymbolAddress((void**)&y1th, g_y1th); cudaGetSymbolAddress((void**)&y1tl, g_y1tl);
    cudaGetSymbolAddress((void**)&y2p, g_y2p);
    cudaGetSymbolAddress((void**)&y2h, g_y2h);  cudaGetSymbolAddress((void**)&y2l, g_y2l);
    cudaGetSymbolAddress((void**)&y2th, g_y2th); cudaGetSymbolAddress((void**)&y2tl, g_y2tl);
    cudaGetSymbolAddress((void**)&sc,  g_sc);
    cudaGetSymbolAddress((void**)&ath, g_ath);  cudaGetSymbolAddress((void**)&atl, g_atl);

    const int SMB = 131072;
    cudaFuncSetAttribute(gemm_cp<0, 256>, cudaFuncAttributeMaxDynamicSharedMemorySize, SMB);
    cudaFuncSetAttribute(gemm_cp<0, 128>, cudaFuncAttributeMaxDynamicSharedMemorySize, SMB);
    cudaFuncSetAttribute(gemm_cp<1, 0>,   cudaFuncAttributeMaxDynamicSharedMemorySize, SMB);
    cudaFuncSetAttribute(gemm_cp<2, 0>,   cudaFuncAttributeMaxDynamicSharedMemorySize, SMB);

    // ---- operand prep ----
    w_reorder<<<(128 * 2304 + 255) / 256, 256>>>(w1, w1h, w1l, 128, 256);
    w_reorder<<<(256 * 1152 + 255) / 256, 256>>>(w2, w2h, w2l, 256, 128);
    x_tr_split<<<dim3(128, 8, 16), dim3(32, 8)>>>(x, xth, xtl);

    // conv1: [B,256,64,64] -> y1 [B,128,64,64]
    gemm_cp<0, 256><<<dim3(32, 1, 16), 256, SMB>>>(
        w1h, w1l, 2304, xth, xtl, 2304, g1, b1, m1, v1, nullptr, y1p, nullptr);
    split_tr<<<dim3(128, 4, 16), dim3(32, 8)>>>(y1p, y1th, y1tl, 128);

    // conv2: -> y2 [B,256,64,64]
    gemm_cp<0, 128><<<dim3(32, 2, 16), 256, SMB>>>(
        w2h, w2l, 1152, y1th, y1tl, 1152, g2, b2, m2, v2, nullptr, y2p, nullptr);
    split_lin<<<(16 * 256 * 4096 / 2 + 255) / 256, 256>>>(y2p, y2h, y2l, 16 * 256 * 4096 / 2);
    split_tr<<<dim3(128, 8, 16), dim3(32, 8)>>>(y2p, y2th, y2tl, 256);

    // scores = (q q^T)/16
    gemm_cp<1, 0><<<dim3(2, 2, 16), 256, SMB>>>(
        y2h, y2l, 4096, y2h, y2l, 4096,
        nullptr, nullptr, nullptr, nullptr, nullptr, nullptr, sc);
    softmax_split<<<4096, 256>>>(sc, ath, atl);

    // out = attn * q + x
    gemm_cp<2, 0><<<dim3(32, 2, 16), 256, SMB>>>(
        ath, atl, 256, y2th, y2tl, 256,
        nullptr, nullptr, nullptr, nullptr, x, nullptr, out);
}

// round 6
// speedup vs baseline: 3.9869x; 1.2374x over previous
#include <cuda_runtime.h>
#include <cuda_bf16.h>
#include <math.h>
#include <stdint.h>

#define BN_EPS 1e-5f

// ---------------------------------------------------------------------------
// Global scratch: hi/lo bf16 planes for all GEMM operands
// ---------------------------------------------------------------------------
__device__ __nv_bfloat16 g_w1h[128*2304],  g_w1l[128*2304];    // k = r*256+ci
__device__ __nv_bfloat16 g_w2h[256*1152],  g_w2l[256*1152];    // k = r*128+ci
__device__ __nv_bfloat16 g_xth[16u*4096*256], g_xtl[16u*4096*256];   // x^T [b][p][ci]
__device__ uint32_t      g_y1p[16u*128*4096];                        // conv1 out packed [b][c][p]
__device__ __nv_bfloat16 g_y1th[16u*4096*128], g_y1tl[16u*4096*128]; // y1^T [b][p][ci]
__device__ uint32_t      g_y2p[16u*256*4096];                        // conv2 out packed [b][c][p]
__device__ __nv_bfloat16 g_y2h[16u*256*4096],  g_y2l[16u*256*4096];  // y2   [b][c][p]
__device__ __nv_bfloat16 g_y2th[16u*4096*256], g_y2tl[16u*4096*256]; // y2^T [b][p][c]
__device__ float         g_sc[16u*256*256];
__device__ __nv_bfloat16 g_ath[16u*256*256], g_atl[16u*256*256];     // attn planes

// ---------------------------------------------------------------------------
__device__ __forceinline__ uint32_t smem_u32(const void* p) {
    uint32_t a;
    asm("{ .reg .u64 t; cvta.to.shared.u64 t, %1; cvt.u32.u64 %0, t; }" : "=r"(a) : "l"(p));
    return a;
}
__device__ __forceinline__ uint32_t pack_hl(float v) {
    __nv_bfloat16 h = __float2bfloat16(v);
    float hf = __bfloat162float(h);
    __nv_bfloat16 l = __float2bfloat16(v - hf);
    return (uint32_t)__bfloat16_as_ushort(h) | ((uint32_t)__bfloat16_as_ushort(l) << 16);
}
__device__ __forceinline__ void ldsm_x4(uint32_t addr, uint32_t r[4]) {
    asm volatile("ldmatrix.sync.aligned.m8n8.x4.shared.b16 {%0,%1,%2,%3}, [%4];"
                 : "=r"(r[0]), "=r"(r[1]), "=r"(r[2]), "=r"(r[3]) : "r"(addr));
}
__device__ __forceinline__ void mma16816(float d[4], const uint32_t a[4],
                                         uint32_t b0, uint32_t b1) {
    asm volatile(
        "mma.sync.aligned.m16n8k16.row.col.f32.bf16.bf16.f32 "
        "{%0,%1,%2,%3}, {%4,%5,%6,%7}, {%8,%9}, {%0,%1,%2,%3};"
        : "+f"(d[0]), "+f"(d[1]), "+f"(d[2]), "+f"(d[3])
        : "r"(a[0]), "r"(a[1]), "r"(a[2]), "r"(a[3]), "r"(b0), "r"(b1));
}
__device__ __forceinline__ uint32_t sw128(uint32_t off) {
    return off ^ ((off >> 3) & 0x70);
}
__device__ __forceinline__ void cp16(uint32_t dst, const void* src, int sz) {
    asm volatile("cp.async.cg.shared.global [%0], [%1], 16, %2;"
                 :: "r"(dst), "l"(src), "r"(sz) : "memory");
}
__device__ __forceinline__ void cp_commit() {
    asm volatile("cp.async.commit_group;" ::: "memory");
}

// ---------------------------------------------------------------------------
// Split-bf16 GEMM on HMMA, cp.async double-buffered, 2 CTAs/SM.
// D tile = [128 (bm), 64 (bn)] = A[128,K] * B[64,K]^T, fp32 accum.
// MODE 0: conv (BN+SiLU -> packed out), B = shifted transposed image planes
// MODE 1: scores (x 1/16 -> fp32)
// MODE 2: out (+ residual -> fp32)
// Stage (48KB): Ah +0, Al +16384, Bh +32768, Bl +40960.
// ---------------------------------------------------------------------------
template <int MODE, int CI>
__global__ __launch_bounds__(256, 2)
void gemm_cp(const __nv_bfloat16* __restrict__ Agh, const __nv_bfloat16* __restrict__ Agl, int lda,
             const __nv_bfloat16* __restrict__ Bgh, const __nv_bfloat16* __restrict__ Bgl, int K,
             const float* __restrict__ p0, const float* __restrict__ p1,
             const float* __restrict__ p2, const float* __restrict__ p3,
             const float* __restrict__ resid,
             uint32_t* __restrict__ outp, float* __restrict__ outf)
{
    extern __shared__ char sm[];
    const int t    = threadIdx.x;
    const int lane = t & 31, warp = t >> 5;
    const int wm   = (warp >> 1) * 32;   // 4 row groups of 32
    const int wn   = (warp & 1) * 32;    // 2 col groups of 32
    const int b = blockIdx.z, bm = blockIdx.y, bn = blockIdx.x;
    const uint32_t sb = smem_u32(sm);

    const __nv_bfloat16 *Abh, *Abl, *Bbh, *Bbl;
    if (MODE == 0) {
        Abh = Agh; Abl = Agl;
        Bbh = Bgh + (size_t)b * 4096 * CI; Bbl = Bgl + (size_t)b * 4096 * CI;
    } else if (MODE == 1) {
        size_t o = (size_t)b * 256 * 4096;
        Abh = Agh + o; Abl = Agl + o; Bbh = Bgh + o; Bbl = Bgl + o;
    } else {
        size_t oa = (size_t)b * 256 * 256, ob = (size_t)b * 4096 * 256;
        Abh = Agh + oa; Abl = Agl + oa; Bbh = Bgh + ob; Bbl = Bgl + ob;
    }
    const int ldb = (MODE == 1) ? 4096 : 256;

    float acc[2][4][4];
#pragma unroll
    for (int i = 0; i < 2; ++i)
#pragma unroll
        for (int j = 0; j < 4; ++j)
#pragma unroll
            for (int q = 0; q < 4; ++q) acc[i][j][q] = 0.f;

    const int a_row = (lane & 7) + ((lane >> 3) & 1) * 8;
    const int a_chk = lane >> 4;
    const int b_row = (lane & 7) + ((lane >> 4) & 1) * 8;
    const int b_chk = (lane >> 3) & 1;

    auto prefetch = [&](int kt, int stage) {
        const uint32_t base = sb + stage * 49152;
        // ---- A planes: 128 rows x 128B ----
#pragma unroll
        for (int i = 0; i < 4; ++i) {
            const int task = t + i * 256, m = task >> 3, g = task & 7;
            const size_t so = (size_t)(bm * 128 + m) * lda + kt * 64 + g * 8;
            const uint32_t d = sw128(m * 128 + g * 16);
            cp16(base + d,         Abh + so, 16);
            cp16(base + 16384 + d, Abl + so, 16);
        }
        // ---- B planes: 64 rows x 128B ----
        if (MODE == 0) {
            constexpr int CPR = CI / 64;
            const int r  = kt / CPR;
            const int ci0 = (kt - r * CPR) * 64;
            const int dh = r / 3 - 1, dw = (r - (r / 3) * 3) - 1;
#pragma unroll
            for (int i = 0; i < 2; ++i) {
                const int task = t + i * 256, m = task >> 3, g = task & 7;
                const int p = bn * 64 + m, h = p >> 6, w = p & 63;
                const int hh = h + dh, ww = w + dw;
                const bool ok = ((unsigned)hh < 64u) && ((unsigned)ww < 64u);
                const size_t so = ok ? (size_t)((hh << 6) + ww) * CI + ci0 + g * 8 : 0;
                const int sz = ok ? 16 : 0;
                const uint32_t d = sw128(m * 128 + g * 16);
                cp16(base + 32768 + d, Bbh + so, sz);
                cp16(base + 40960 + d, Bbl + so, sz);
            }
        } else {
#pragma unroll
            for (int i = 0; i < 2; ++i) {
                const int task = t + i * 256, m = task >> 3, g = task & 7;
                const size_t so = (size_t)(bn * 64 + m) * ldb + kt * 64 + g * 8;
                const uint32_t d = sw128(m * 128 + g * 16);
                cp16(base + 32768 + d, Bbh + so, 16);
                cp16(base + 40960 + d, Bbl + so, 16);
            }
        }
    };

    const int nch = K / 64;
    prefetch(0, 0);
    cp_commit();

    for (int kt = 0; kt < nch; ++kt) {
        const int stage = kt & 1;
        if (kt + 1 < nch) {
            prefetch(kt + 1, stage ^ 1);
            cp_commit();
            asm volatile("cp.async.wait_group 1;" ::: "memory");
        } else {
            asm volatile("cp.async.wait_group 0;" ::: "memory");
        }
        __syncthreads();

        const uint32_t base = sb + stage * 49152;
#pragma unroll
        for (int ks = 0; ks < 4; ++ks) {
            uint32_t ah[2][4], al[2][4];
#pragma unroll
            for (int mt = 0; mt < 2; ++mt) {
                uint32_t off = sw128((wm + mt * 16 + a_row) * 128 + (ks * 2 + a_chk) * 16);
                ldsm_x4(base + off,         ah[mt]);
                ldsm_x4(base + 16384 + off, al[mt]);
            }
#pragma unroll
            for (int ng = 0; ng < 2; ++ng) {
                uint32_t bh[4], bl[4];
                uint32_t off = sw128((wn + ng * 16 + b_row) * 128 + (ks * 2 + b_chk) * 16);
                ldsm_x4(base + 32768 + off, bh);
                ldsm_x4(base + 40960 + off, bl);
#pragma unroll
                for (int mt = 0; mt < 2; ++mt) {
                    mma16816(acc[mt][2 * ng],     ah[mt], bh[0], bh[1]);
                    mma16816(acc[mt][2 * ng],     ah[mt], bl[0], bl[1]);
                    mma16816(acc[mt][2 * ng],     al[mt], bh[0], bh[1]);
                    mma16816(acc[mt][2 * ng + 1], ah[mt], bh[2], bh[3]);
                    mma16816(acc[mt][2 * ng + 1], ah[mt], bl[2], bl[3]);
                    mma16816(acc[mt][2 * ng + 1], al[mt], bh[2], bh[3]);
                }
            }
        }
        __syncthreads();
    }

    // ----------------------- epilogue -----------------------
    const int r0 = bm * 128 + wm + (lane >> 2);
    const int c0 = bn * 64 + wn + (lane & 3) * 2;

    if (MODE == 0) {
        const int CO = gridDim.y * 128;
#pragma unroll
        for (int mt = 0; mt < 2; ++mt) {
#pragma unroll
            for (int half = 0; half < 2; ++half) {
                const int co = r0 + mt * 16 + half * 8;
                const float scl = p0[co] * rsqrtf(p3[co] + BN_EPS);
                const float shf = p1[co] - p2[co] * scl;
                uint32_t* dst = outp + ((size_t)(b * CO + co)) * 4096;
#pragma unroll
                for (int nt = 0; nt < 4; ++nt) {
                    float y0 = acc[mt][nt][2 * half]     * scl + shf;
                    float y1 = acc[mt][nt][2 * half + 1] * scl + shf;
                    y0 = y0 / (1.f + expf(-y0));
                    y1 = y1 / (1.f + expf(-y1));
                    *reinterpret_cast<uint2*>(dst + c0 + nt * 8) =
                        make_uint2(pack_hl(y0), pack_hl(y1));
                }
            }
        }
    } else if (MODE == 1) {
#pragma unroll
        for (int mt = 0; mt < 2; ++mt) {
#pragma unroll
            for (int half = 0; half < 2; ++half) {
                const int c = r0 + mt * 16 + half * 8;
                float* dst = outf + ((size_t)b * 256 + c) * 256;
#pragma unroll
                for (int nt = 0; nt < 4; ++nt) {
                    *reinterpret_cast<float2*>(dst + c0 + nt * 8) =
                        make_float2(acc[mt][nt][2 * half] * 0.0625f,
                                    acc[mt][nt][2 * half + 1] * 0.0625f);
                }
            }
        }
    } else {
#pragma unroll
        for (int mt = 0; mt < 2; ++mt) {
#pragma unroll
            for (int half = 0; half < 2; ++half) {
                const int c = r0 + mt * 16 + half * 8;
                const size_t base2 = ((size_t)(b * 256 + c)) * 4096;
#pragma unroll
                for (int nt = 0; nt < 4; ++nt) {
                    float2 rx = *reinterpret_cast<const float2*>(resid + base2 + c0 + nt * 8);
                    *reinterpret_cast<float2*>(outf + base2 + c0 + nt * 8) =
                        make_float2(acc[mt][nt][2 * half] + rx.x,
                                    acc[mt][nt][2 * half + 1] + rx.y);
                }
            }
        }
    }
}

// ---------------------------------------------------------------------------
// Pack / reorder helpers
// ---------------------------------------------------------------------------
__global__ __launch_bounds__(256) void w_reorder(const float* __restrict__ w,
                                                 __nv_bfloat16* __restrict__ wh,
                                                 __nv_bfloat16* __restrict__ wl,
                                                 int CO, int CIc) {
    int idx = blockIdx.x * 256 + threadIdx.x;
    int total = CO * CIc * 9;
    if (idx >= total) return;
    int K  = CIc * 9;
    int co = idx / K;
    int rem = idx - co * K;
    int r  = rem / CIc;
    int ci = rem - r * CIc;
    uint32_t pl = pack_hl(w[(size_t)co * K + ci * 9 + r]);
    wh[idx] = __ushort_as_bfloat16((uint16_t)pl);
    wl[idx] = __ushort_as_bfloat16((uint16_t)(pl >> 16));
}

__global__ void x_tr_split(const float* __restrict__ x,
                           __nv_bfloat16* __restrict__ xh, __nv_bfloat16* __restrict__ xl) {
    __shared__ float tile[32][33];
    const int b = blockIdx.z, p0 = blockIdx.x * 32, c0 = blockIdx.y * 32;
    const float* s = x + (size_t)b * 256 * 4096;
    const int tx = threadIdx.x, ty = threadIdx.y;
#pragma unroll
    for (int i = ty; i < 32; i += 8) tile[i][tx] = s[(size_t)(c0 + i) * 4096 + p0 + tx];
    __syncthreads();
#pragma unroll
    for (int i = ty; i < 32; i += 8) {
        uint32_t pl = pack_hl(tile[tx][i]);
        size_t d = (size_t)(b * 4096 + p0 + i) * 256 + c0 + tx;
        xh[d] = __ushort_as_bfloat16((uint16_t)pl);
        xl[d] = __ushort_as_bfloat16((uint16_t)(pl >> 16));
    }
}

__global__ void split_tr(const uint32_t* __restrict__ src,
                         __nv_bfloat16* __restrict__ th, __nv_bfloat16* __restrict__ tl, int C) {
    __shared__ uint32_t tile[32][33];
    const int b = blockIdx.z, p0 = blockIdx.x * 32, c0 = blockIdx.y * 32;
    const uint32_t* s = src + (size_t)b * C * 4096;
    const int tx = threadIdx.x, ty = threadIdx.y;
#pragma unroll
    for (int i = ty; i < 32; i += 8) tile[i][tx] = s[(size_t)(c0 + i) * 4096 + p0 + tx];
    __syncthreads();
#pragma unroll
    for (int i = ty; i < 32; i += 8) {
        uint32_t v = tile[tx][i];
        size_t d = (size_t)(b * 4096 + p0 + i) * C + c0 + tx;
        th[d] = __ushort_as_bfloat16((uint16_t)v);
        tl[d] = __ushort_as_bfloat16((uint16_t)(v >> 16));
    }
}

__global__ __launch_bounds__(256) void split_lin(const uint32_t* __restrict__ src,
                                                 __nv_bfloat16* __restrict__ h,
                                                 __nv_bfloat16* __restrict__ l, int n2) {
    int i = blockIdx.x * 256 + threadIdx.x;
    if (i < n2) {
        uint2 v = reinterpret_cast<const uint2*>(src)[i];
        uint32_t hp = (v.x & 0xFFFFu) | (v.y << 16);
        uint32_t lp = (v.x >> 16) | (v.y & 0xFFFF0000u);
        reinterpret_cast<uint32_t*>(h)[i] = hp;
        reinterpret_cast<uint32_t*>(l)[i] = lp;
    }
}

__global__ __launch_bounds__(256) void softmax_split(const float* __restrict__ s,
                                                     __nv_bfloat16* __restrict__ ah,
                                                     __nv_bfloat16* __restrict__ al) {
    __shared__ float redmax[8];
    __shared__ float redsum[8];
    const float* r = s + (size_t)blockIdx.x * 256;
    const int t = threadIdx.x;

    float v = r[t];
    float m = v;
#pragma unroll
    for (int o = 16; o; o >>= 1) m = fmaxf(m, __shfl_xor_sync(0xffffffffu, m, o));
    if ((t & 31) == 0) redmax[t >> 5] = m;
    __syncthreads();
    m = redmax[0];
#pragma unroll
    for (int i = 1; i < 8; ++i) m = fmaxf(m, redmax[i]);

    float e = expf(v - m);
    float sum = e;
#pragma unroll
    for (int o = 16; o; o >>= 1) sum += __shfl_xor_sync(0xffffffffu, sum, o);
    if ((t & 31) == 0) redsum[t >> 5] = sum;
    __syncthreads();
    sum = 0.f;
#pragma unroll
    for (int i = 0; i < 8; ++i) sum += redsum[i];

    uint32_t pl = pack_hl(e / sum);
    size_t idx = (size_t)blockIdx.x * 256 + t;
    ah[idx] = __ushort_as_bfloat16((uint16_t)pl);
    al[idx] = __ushort_as_bfloat16((uint16_t)(pl >> 16));
}

// ---------------------------------------------------------------------------
extern "C" void kernel_launch(void* const* d_in, const int* in_sizes, int n_in,
                              void* d_out, int out_size)
{
    const float* x  = (const float*)d_in[0];
    const float* w1 = (const float*)d_in[1];
    const float* g1 = (const float*)d_in[2];
    const float* b1 = (const float*)d_in[3];
    const float* m1 = (const float*)d_in[4];
    const float* v1 = (const float*)d_in[5];
    const float* w2 = (const float*)d_in[6];
    const float* g2 = (const float*)d_in[7];
    const float* b2 = (const float*)d_in[8];
    const float* m2 = (const float*)d_in[9];
    const float* v2 = (const float*)d_in[10];
    float* out = (float*)d_out;

    __nv_bfloat16 *w1h, *w1l, *w2h, *w2l, *xth, *xtl, *y1th, *y1tl;
    __nv_bfloat16 *y2h, *y2l, *y2th, *y2tl, *ath, *atl;
    uint32_t *y1p, *y2p;
    float* sc;
    cudaGetSymbolAddress((void**)&w1h, g_w1h);  cudaGetSymbolAddress((void**)&w1l, g_w1l);
    cudaGetSymbolAddress((void**)&w2h, g_w2h);  cudaGetSymbolAddress((void**)&w2l, g_w2l);
    cudaGetSymbolAddress((void**)&xth, g_xth);  cudaGetSymbolAddress((void**)&xtl, g_xtl);
    cudaGetSymbolAddress((void**)&y1p, g_y1p);
    cudaGetSymbolAddress((void**)&y1th, g_y1th); cudaGetSymbolAddress((void**)&y1tl, g_y1tl);
    cudaGetSymbolAddress((void**)&y2p, g_y2p);
    cudaGetSymbolAddress((void**)&y2h, g_y2h);  cudaGetSymbolAddress((void**)&y2l, g_y2l);
    cudaGetSymbolAddress((void**)&y2th, g_y2th); cudaGetSymbolAddress((void**)&y2tl, g_y2tl);
    cudaGetSymbolAddress((void**)&sc,  g_sc);
    cudaGetSymbolAddress((void**)&ath, g_ath);  cudaGetSymbolAddress((void**)&atl, g_atl);

    const int SMB = 98304;   // 2 stages x 48KB
    cudaFuncSetAttribute(gemm_cp<0, 256>, cudaFuncAttributeMaxDynamicSharedMemorySize, SMB);
    cudaFuncSetAttribute(gemm_cp<0, 128>, cudaFuncAttributeMaxDynamicSharedMemorySize, SMB);
    cudaFuncSetAttribute(gemm_cp<1, 0>,   cudaFuncAttributeMaxDynamicSharedMemorySize, SMB);
    cudaFuncSetAttribute(gemm_cp<2, 0>,   cudaFuncAttributeMaxDynamicSharedMemorySize, SMB);

    // ---- operand prep ----
    w_reorder<<<(128 * 2304 + 255) / 256, 256>>>(w1, w1h, w1l, 128, 256);
    w_reorder<<<(256 * 1152 + 255) / 256, 256>>>(w2, w2h, w2l, 256, 128);
    x_tr_split<<<dim3(128, 8, 16), dim3(32, 8)>>>(x, xth, xtl);

    // conv1: [B,256,64,64] -> y1 [B,128,64,64]
    gemm_cp<0, 256><<<dim3(64, 1, 16), 256, SMB>>>(
        w1h, w1l, 2304, xth, xtl, 2304, g1, b1, m1, v1, nullptr, y1p, nullptr);
    split_tr<<<dim3(128, 4, 16), dim3(32, 8)>>>(y1p, y1th, y1tl, 128);

    // conv2: -> y2 [B,256,64,64]
    gemm_cp<0, 128><<<dim3(64, 2, 16), 256, SMB>>>(
        w2h, w2l, 1152, y1th, y1tl, 1152, g2, b2, m2, v2, nullptr, y2p, nullptr);
    split_lin<<<(16 * 256 * 4096 / 2 + 255) / 256, 256>>>(y2p, y2h, y2l, 16 * 256 * 4096 / 2);
    split_tr<<<dim3(128, 8, 16), dim3(32, 8)>>>(y2p, y2th, y2tl, 256);

    // scores = (q q^T)/16
    gemm_cp<1, 0><<<dim3(4, 2, 16), 256, SMB>>>(
        y2h, y2l, 4096, y2h, y2l, 4096,
        nullptr, nullptr, nullptr, nullptr, nullptr, nullptr, sc);
    softmax_split<<<4096, 256>>>(sc, ath, atl);

    // out = attn * q + x
    gemm_cp<2, 0><<<dim3(64, 2, 16), 256, SMB>>>(
        ath, atl, 256, y2th, y2tl, 256,
        nullptr, nullptr, nullptr, nullptr, x, nullptr, out);
}

// round 7
// speedup vs baseline: 8.6868x; 2.1788x over previous
#include <cuda_runtime.h>
#include <cuda_fp16.h>
#include <math.h>
#include <stdint.h>

#define BN_EPS 1e-5f

// ---------------------------------------------------------------------------
// Global scratch: fp16 operands
// ---------------------------------------------------------------------------
__device__ __half g_w1h[128*2304];                 // k = r*256+ci
__device__ __half g_w2h[256*1152];                 // k = r*128+ci
__device__ __half g_xt [16u*4096*256];             // x^T  [b][p][ci]
__device__ __half g_y1 [16u*128*4096];             // y1   [b][c][p]
__device__ __half g_y1t[16u*4096*128];             // y1^T [b][p][ci]
__device__ __half g_y2 [16u*256*4096];             // y2   [b][c][p]
__device__ __half g_y2t[16u*4096*256];             // y2^T [b][p][c]
__device__ float  g_sc [16u*256*256];
__device__ __half g_at [16u*256*256];              // attn

// ---------------------------------------------------------------------------
__device__ __forceinline__ uint32_t smem_u32(const void* p) {
    uint32_t a;
    asm("{ .reg .u64 t; cvta.to.shared.u64 t, %1; cvt.u32.u64 %0, t; }" : "=r"(a) : "l"(p));
    return a;
}
__device__ __forceinline__ void ldsm_x4(uint32_t addr, uint32_t r[4]) {
    asm volatile("ldmatrix.sync.aligned.m8n8.x4.shared.b16 {%0,%1,%2,%3}, [%4];"
                 : "=r"(r[0]), "=r"(r[1]), "=r"(r[2]), "=r"(r[3]) : "r"(addr));
}
__device__ __forceinline__ void mma16816(float d[4], const uint32_t a[4],
                                         uint32_t b0, uint32_t b1) {
    asm volatile(
        "mma.sync.aligned.m16n8k16.row.col.f32.f16.f16.f32 "
        "{%0,%1,%2,%3}, {%4,%5,%6,%7}, {%8,%9}, {%0,%1,%2,%3};"
        : "+f"(d[0]), "+f"(d[1]), "+f"(d[2]), "+f"(d[3])
        : "r"(a[0]), "r"(a[1]), "r"(a[2]), "r"(a[3]), "r"(b0), "r"(b1));
}
__device__ __forceinline__ uint32_t sw128(uint32_t off) {
    return off ^ ((off >> 3) & 0x70);
}
__device__ __forceinline__ void cp16(uint32_t dst, const void* src, int sz) {
    asm volatile("cp.async.cg.shared.global [%0], [%1], 16, %2;"
                 :: "r"(dst), "l"(src), "r"(sz) : "memory");
}
__device__ __forceinline__ void cp_commit() {
    asm volatile("cp.async.commit_group;" ::: "memory");
}

// ---------------------------------------------------------------------------
// fp16 GEMM on HMMA, cp.async double-buffered, 2 CTAs/SM.
// D tile = [128 (bm), 64 (bn)] = A[128,K] * B[64,K]^T, fp32 accum.
// MODE 0: conv (BN+SiLU -> fp16 out), B = shifted transposed image planes
// MODE 1: scores (x 1/16 -> fp32)
// MODE 2: out (+ residual -> fp32)
// Stage (24KB): A +0 (16KB), B +16384 (8KB).
// ---------------------------------------------------------------------------
template <int MODE, int CI>
__global__ __launch_bounds__(256, 2)
void gemm_fp16(const __half* __restrict__ Ag, int lda,
               const __half* __restrict__ Bg, int K,
               const float* __restrict__ p0, const float* __restrict__ p1,
               const float* __restrict__ p2, const float* __restrict__ p3,
               const float* __restrict__ resid,
               __half* __restrict__ outh, float* __restrict__ outf)
{
    extern __shared__ char sm[];
    const int t    = threadIdx.x;
    const int lane = t & 31, warp = t >> 5;
    const int wm   = (warp >> 1) * 32;   // 4 row groups of 32
    const int wn   = (warp & 1) * 32;    // 2 col groups of 32
    const int b = blockIdx.z, bm = blockIdx.y, bn = blockIdx.x;
    const uint32_t sb = smem_u32(sm);

    const __half *Ab, *Bb;
    if (MODE == 0) {
        Ab = Ag; Bb = Bg + (size_t)b * 4096 * CI;
    } else if (MODE == 1) {
        size_t o = (size_t)b * 256 * 4096;
        Ab = Ag + o; Bb = Bg + o;
    } else {
        Ab = Ag + (size_t)b * 256 * 256; Bb = Bg + (size_t)b * 4096 * 256;
    }
    const int ldb = (MODE == 1) ? 4096 : 256;

    float acc[2][4][4];
#pragma unroll
    for (int i = 0; i < 2; ++i)
#pragma unroll
        for (int j = 0; j < 4; ++j)
#pragma unroll
            for (int q = 0; q < 4; ++q) acc[i][j][q] = 0.f;

    const int a_row = (lane & 7) + ((lane >> 3) & 1) * 8;
    const int a_chk = lane >> 4;
    const int b_row = (lane & 7) + ((lane >> 4) & 1) * 8;
    const int b_chk = (lane >> 3) & 1;

    auto prefetch = [&](int kt, int stage) {
        const uint32_t base = sb + stage * 24576;
        // ---- A: 128 rows x 128B ----
#pragma unroll
        for (int i = 0; i < 4; ++i) {
            const int task = t + i * 256, m = task >> 3, g = task & 7;
            const size_t so = (size_t)(bm * 128 + m) * lda + kt * 64 + g * 8;
            cp16(base + sw128(m * 128 + g * 16), Ab + so, 16);
        }
        // ---- B: 64 rows x 128B ----
        if (MODE == 0) {
            constexpr int CPR = CI / 64;
            const int r  = kt / CPR;
            const int ci0 = (kt - r * CPR) * 64;
            const int dh = r / 3 - 1, dw = (r - (r / 3) * 3) - 1;
#pragma unroll
            for (int i = 0; i < 2; ++i) {
                const int task = t + i * 256, m = task >> 3, g = task & 7;
                const int p = bn * 64 + m, h = p >> 6, w = p & 63;
                const int hh = h + dh, ww = w + dw;
                const bool ok = ((unsigned)hh < 64u) && ((unsigned)ww < 64u);
                const size_t so = ok ? (size_t)((hh << 6) + ww) * CI + ci0 + g * 8 : 0;
                cp16(base + 16384 + sw128(m * 128 + g * 16), Bb + so, ok ? 16 : 0);
            }
        } else {
#pragma unroll
            for (int i = 0; i < 2; ++i) {
                const int task = t + i * 256, m = task >> 3, g = task & 7;
                const size_t so = (size_t)(bn * 64 + m) * ldb + kt * 64 + g * 8;
                cp16(base + 16384 + sw128(m * 128 + g * 16), Bb + so, 16);
            }
        }
    };

    const int nch = K / 64;
    prefetch(0, 0);
    cp_commit();

    for (int kt = 0; kt < nch; ++kt) {
        const int stage = kt & 1;
        if (kt + 1 < nch) {
            prefetch(kt + 1, stage ^ 1);
            cp_commit();
            asm volatile("cp.async.wait_group 1;" ::: "memory");
        } else {
            asm volatile("cp.async.wait_group 0;" ::: "memory");
        }
        __syncthreads();

        const uint32_t base = sb + stage * 24576;
#pragma unroll
        for (int ks = 0; ks < 4; ++ks) {
            uint32_t ah[2][4];
#pragma unroll
            for (int mt = 0; mt < 2; ++mt) {
                uint32_t off = sw128((wm + mt * 16 + a_row) * 128 + (ks * 2 + a_chk) * 16);
                ldsm_x4(base + off, ah[mt]);
            }
#pragma unroll
            for (int ng = 0; ng < 2; ++ng) {
                uint32_t bh[4];
                uint32_t off = sw128((wn + ng * 16 + b_row) * 128 + (ks * 2 + b_chk) * 16);
                ldsm_x4(base + 16384 + off, bh);
#pragma unroll
                for (int mt = 0; mt < 2; ++mt) {
                    mma16816(acc[mt][2 * ng],     ah[mt], bh[0], bh[1]);
                    mma16816(acc[mt][2 * ng + 1], ah[mt], bh[2], bh[3]);
                }
            }
        }
        __syncthreads();
    }

    // ----------------------- epilogue -----------------------
    const int r0 = bm * 128 + wm + (lane >> 2);
    const int c0 = bn * 64 + wn + (lane & 3) * 2;

    if (MODE == 0) {
        const int CO = gridDim.y * 128;
#pragma unroll
        for (int mt = 0; mt < 2; ++mt) {
#pragma unroll
            for (int half = 0; half < 2; ++half) {
                const int co = r0 + mt * 16 + half * 8;
                const float scl = p0[co] * rsqrtf(p3[co] + BN_EPS);
                const float shf = p1[co] - p2[co] * scl;
                __half* dst = outh + ((size_t)(b * CO + co)) * 4096;
#pragma unroll
                for (int nt = 0; nt < 4; ++nt) {
                    float y0 = acc[mt][nt][2 * half]     * scl + shf;
                    float y1 = acc[mt][nt][2 * half + 1] * scl + shf;
                    y0 = y0 / (1.f + expf(-y0));
                    y1 = y1 / (1.f + expf(-y1));
                    *reinterpret_cast<__half2*>(dst + c0 + nt * 8) =
                        __floats2half2_rn(y0, y1);
                }
            }
        }
    } else if (MODE == 1) {
#pragma unroll
        for (int mt = 0; mt < 2; ++mt) {
#pragma unroll
            for (int half = 0; half < 2; ++half) {
                const int c = r0 + mt * 16 + half * 8;
                float* dst = outf + ((size_t)b * 256 + c) * 256;
#pragma unroll
                for (int nt = 0; nt < 4; ++nt) {
                    *reinterpret_cast<float2*>(dst + c0 + nt * 8) =
                        make_float2(acc[mt][nt][2 * half] * 0.0625f,
                                    acc[mt][nt][2 * half + 1] * 0.0625f);
                }
            }
        }
    } else {
#pragma unroll
        for (int mt = 0; mt < 2; ++mt) {
#pragma unroll
            for (int half = 0; half < 2; ++half) {
                const int c = r0 + mt * 16 + half * 8;
                const size_t base2 = ((size_t)(b * 256 + c)) * 4096;
#pragma unroll
                for (int nt = 0; nt < 4; ++nt) {
                    float2 rx = *reinterpret_cast<const float2*>(resid + base2 + c0 + nt * 8);
                    *reinterpret_cast<float2*>(outf + base2 + c0 + nt * 8) =
                        make_float2(acc[mt][nt][2 * half] + rx.x,
                                    acc[mt][nt][2 * half + 1] + rx.y);
                }
            }
        }
    }
}

// ---------------------------------------------------------------------------
// Helpers
// ---------------------------------------------------------------------------
// weights OIHW [co][ci][3][3] -> [co][r*CI+ci] fp16
__global__ __launch_bounds__(256) void w_reorder(const float* __restrict__ w,
                                                 __half* __restrict__ wh,
                                                 int CO, int CIc) {
    int idx = blockIdx.x * 256 + threadIdx.x;
    int total = CO * CIc * 9;
    if (idx >= total) return;
    int K  = CIc * 9;
    int co = idx / K;
    int rem = idx - co * K;
    int r  = rem / CIc;
    int ci = rem - r * CIc;
    wh[idx] = __float2half_rn(w[(size_t)co * K + ci * 9 + r]);
}

// x fp32 [b][256][4096] -> x^T fp16 [b][p][256].  Tile: 64 c x 32 p.
__global__ __launch_bounds__(256) void x_tr(const float* __restrict__ x,
                                            __half* __restrict__ xt) {
    __shared__ uint16_t tile[64][65];
    const int b = blockIdx.z, p0 = blockIdx.x * 32, c0 = blockIdx.y * 64;
    const float* s = x + (size_t)b * 256 * 4096;
    const int t = threadIdx.x;
#pragma unroll
    for (int i = 0; i < 8; ++i) {
        int task = t + i * 256;          // 2048: 64 c rows x 32 p
        int c = task >> 5, p = task & 31;
        tile[c][p] = __half_as_ushort(__float2half_rn(s[(size_t)(c0 + c) * 4096 + p0 + p]));
    }
    __syncthreads();
#pragma unroll
    for (int i = 0; i < 4; ++i) {
        int task = t + i * 256;          // 1024: 32 p rows x 32 c-pairs
        int p = task >> 5, c2 = task & 31;
        uint32_t v = (uint32_t)tile[2 * c2][p] | ((uint32_t)tile[2 * c2 + 1][p] << 16);
        *reinterpret_cast<uint32_t*>(xt + (size_t)(b * 4096 + p0 + p) * 256 + c0 + 2 * c2) = v;
    }
}

// fp16 [b][C][4096] -> fp16 [b][p][C].  Tile: 64 c x 64 p.
__global__ __launch_bounds__(256) void h_tr(const __half* __restrict__ src,
                                            __half* __restrict__ dst, int C) {
    __shared__ uint16_t tile[64][65];
    const int b = blockIdx.z, p0 = blockIdx.x * 64, c0 = blockIdx.y * 64;
    const __half* s = src + (size_t)b * C * 4096;
    __half*       d = dst + (size_t)b * 4096 * C;
    const int t = threadIdx.x;
#pragma unroll
    for (int i = 0; i < 8; ++i) {
        int task = t + i * 256;          // 2048: 64 c rows x 32 p-pairs
        int c = task >> 5, p2 = task & 31;
        uint32_t v = *reinterpret_cast<const uint32_t*>(s + (size_t)(c0 + c) * 4096 + p0 + 2 * p2);
        tile[c][2 * p2]     = (uint16_t)v;
        tile[c][2 * p2 + 1] = (uint16_t)(v >> 16);
    }
    __syncthreads();
#pragma unroll
    for (int i = 0; i < 8; ++i) {
        int task = t + i * 256;          // 2048: 64 p rows x 32 c-pairs
        int p = task >> 5, c2 = task & 31;
        uint32_t v = (uint32_t)tile[2 * c2][p] | ((uint32_t)tile[2 * c2 + 1][p] << 16);
        *reinterpret_cast<uint32_t*>(d + (size_t)(p0 + p) * C + c0 + 2 * c2) = v;
    }
}

__global__ __launch_bounds__(256) void softmax_h(const float* __restrict__ s,
                                                 __half* __restrict__ a) {
    __shared__ float redmax[8];
    __shared__ float redsum[8];
    const float* r = s + (size_t)blockIdx.x * 256;
    const int t = threadIdx.x;

    float v = r[t];
    float m = v;
#pragma unroll
    for (int o = 16; o; o >>= 1) m = fmaxf(m, __shfl_xor_sync(0xffffffffu, m, o));
    if ((t & 31) == 0) redmax[t >> 5] = m;
    __syncthreads();
    m = redmax[0];
#pragma unroll
    for (int i = 1; i < 8; ++i) m = fmaxf(m, redmax[i]);

    float e = expf(v - m);
    float sum = e;
#pragma unroll
    for (int o = 16; o; o >>= 1) sum += __shfl_xor_sync(0xffffffffu, sum, o);
    if ((t & 31) == 0) redsum[t >> 5] = sum;
    __syncthreads();
    sum = 0.f;
#pragma unroll
    for (int i = 0; i < 8; ++i) sum += redsum[i];

    a[(size_t)blockIdx.x * 256 + t] = __float2half_rn(e / sum);
}

// ---------------------------------------------------------------------------
extern "C" void kernel_launch(void* const* d_in, const int* in_sizes, int n_in,
                              void* d_out, int out_size)
{
    const float* x  = (const float*)d_in[0];
    const float* w1 = (const float*)d_in[1];
    const float* g1 = (const float*)d_in[2];
    const float* b1 = (const float*)d_in[3];
    const float* m1 = (const float*)d_in[4];
    const float* v1 = (const float*)d_in[5];
    const float* w2 = (const float*)d_in[6];
    const float* g2 = (const float*)d_in[7];
    const float* b2 = (const float*)d_in[8];
    const float* m2 = (const float*)d_in[9];
    const float* v2 = (const float*)d_in[10];
    float* out = (float*)d_out;

    __half *w1h, *w2h, *xt, *y1, *y1t, *y2, *y2t, *at;
    float* sc;
    cudaGetSymbolAddress((void**)&w1h, g_w1h);
    cudaGetSymbolAddress((void**)&w2h, g_w2h);
    cudaGetSymbolAddress((void**)&xt,  g_xt);
    cudaGetSymbolAddress((void**)&y1,  g_y1);
    cudaGetSymbolAddress((void**)&y1t, g_y1t);
    cudaGetSymbolAddress((void**)&y2,  g_y2);
    cudaGetSymbolAddress((void**)&y2t, g_y2t);
    cudaGetSymbolAddress((void**)&sc,  g_sc);
    cudaGetSymbolAddress((void**)&at,  g_at);

    const int SMB = 49152;   // 2 stages x 24KB
    cudaFuncSetAttribute(gemm_fp16<0, 256>, cudaFuncAttributeMaxDynamicSharedMemorySize, SMB);
    cudaFuncSetAttribute(gemm_fp16<0, 128>, cudaFuncAttributeMaxDynamicSharedMemorySize, SMB);
    cudaFuncSetAttribute(gemm_fp16<1, 0>,   cudaFuncAttributeMaxDynamicSharedMemorySize, SMB);
    cudaFuncSetAttribute(gemm_fp16<2, 0>,   cudaFuncAttributeMaxDynamicSharedMemorySize, SMB);

    // ---- operand prep ----
    w_reorder<<<(128 * 2304 + 255) / 256, 256>>>(w1, w1h, 128, 256);
    w_reorder<<<(256 * 1152 + 255) / 256, 256>>>(w2, w2h, 256, 128);
    x_tr<<<dim3(128, 4, 16), 256>>>(x, xt);

    // conv1: [B,256,64,64] -> y1 [B,128,64,64]
    gemm_fp16<0, 256><<<dim3(64, 1, 16), 256, SMB>>>(
        w1h, 2304, xt, 2304, g1, b1, m1, v1, nullptr, y1, nullptr);
    h_tr<<<dim3(64, 2, 16), 256>>>(y1, y1t, 128);

    // conv2: -> y2 [B,256,64,64]
    gemm_fp16<0, 128><<<dim3(64, 2, 16), 256, SMB>>>(
        w2h, 1152, y1t, 1152, g2, b2, m2, v2, nullptr, y2, nullptr);
    h_tr<<<dim3(64, 4, 16), 256>>>(y2, y2t, 256);

    // scores = (q q^T)/16
    gemm_fp16<1, 0><<<dim3(4, 2, 16), 256, SMB>>>(
        y2, 4096, y2, 4096, nullptr, nullptr, nullptr, nullptr, nullptr, nullptr, sc);
    softmax_h<<<4096, 256>>>(sc, at);

    // out = attn * q + x
    gemm_fp16<2, 0><<<dim3(64, 2, 16), 256, SMB>>>(
        at, 256, y2t, 256, nullptr, nullptr, nullptr, nullptr, x, nullptr, out);
}